// round 2
// baseline (speedup 1.0000x reference)
#include <cuda_runtime.h>
#include <cuda_bf16.h>
#include <cstdint>

// Problem constants (B=2, S=2048, D=4096, H=32, HD=128)
#define BQ   2
#define SQ   2048
#define DIM  4096
#define NH   32
#define HD   128
#define NBH  (BQ*NH)          // 64 batch-heads
#define NPAIR (HD/2)          // 64 rope pairs

// ---------------- scratch (static __device__; no allocation) ----------------
__device__ float g_tmpq[(size_t)BQ*SQ*DIM];   // also reused as attn output
__device__ float g_tmpk[(size_t)BQ*SQ*DIM];
__device__ float g_tmpv[(size_t)BQ*SQ*DIM];
__device__ float g_q   [(size_t)BQ*NH*SQ*HD];
__device__ float g_k   [(size_t)BQ*NH*SQ*HD];
__device__ float g_vT  [(size_t)BQ*NH*HD*SQ];
__device__ float g_scores[(size_t)NBH*SQ*SQ];   // 1 GB

// ---------------- GEMM config ----------------
#define BM 128
#define BN 128
#define BK 32
#define PAD_U 17                      // 16 uint32 (32 bf16) + 1 pad per row
#define TILE_U (BM*PAD_U)             // uints per sub-tile
#define STAGE_U (4*TILE_U)            // Ahi, Alo, Bhi, Blo
#define SMEM_BYTES (2*STAGE_U*4)      // 2 stages = 69632 B

struct GemmParams {
    const float* A; const float* B; float* C;
    int K, lda, ldb, ldc;
    long sAb, sAh, sBb, sBh, sCb, sCh;
    int HB;       // heads per batch for z decomposition
    float scale;
};

__device__ __forceinline__ void mma16816(float* c, const uint32_t* a, uint32_t b0, uint32_t b1) {
    asm volatile(
        "mma.sync.aligned.m16n8k16.row.col.f32.bf16.bf16.f32 "
        "{%0,%1,%2,%3}, {%4,%5,%6,%7}, {%8,%9}, {%0,%1,%2,%3};\n"
        : "+f"(c[0]), "+f"(c[1]), "+f"(c[2]), "+f"(c[3])
        : "r"(a[0]), "r"(a[1]), "r"(a[2]), "r"(a[3]), "r"(b0), "r"(b1));
}

__device__ __forceinline__ uint32_t pack_bf16x2(__nv_bfloat16 e, __nv_bfloat16 o) {
    return (uint32_t)__bfloat16_as_ushort(e) | ((uint32_t)__bfloat16_as_ushort(o) << 16);
}

// Convert staged fp32 tiles to {hi,lo} bf16 pairs and store to smem stage.
__device__ __forceinline__ void sts_tile(uint32_t* sm, int stg,
                                         const float4* ar, const float4* br,
                                         int r0, int c4) {
    uint32_t* base = sm + stg * STAGE_U;
#pragma unroll
    for (int ab = 0; ab < 2; ab++) {
        uint32_t* hi = base + ab * 2 * TILE_U;
        uint32_t* lo = hi + TILE_U;
        const float4* src = ab ? br : ar;
#pragma unroll
        for (int i = 0; i < 4; i++) {
            float f0 = src[i].x, f1 = src[i].y, f2 = src[i].z, f3 = src[i].w;
            __nv_bfloat16 h0 = __float2bfloat16(f0);
            __nv_bfloat16 h1 = __float2bfloat16(f1);
            __nv_bfloat16 h2 = __float2bfloat16(f2);
            __nv_bfloat16 h3 = __float2bfloat16(f3);
            __nv_bfloat16 l0 = __float2bfloat16(f0 - __bfloat162float(h0));
            __nv_bfloat16 l1 = __float2bfloat16(f1 - __bfloat162float(h1));
            __nv_bfloat16 l2 = __float2bfloat16(f2 - __bfloat162float(h2));
            __nv_bfloat16 l3 = __float2bfloat16(f3 - __bfloat162float(h3));
            int ro = (r0 + 32 * i) * PAD_U + c4 * 2;
            hi[ro]     = pack_bf16x2(h0, h1);
            hi[ro + 1] = pack_bf16x2(h2, h3);
            lo[ro]     = pack_bf16x2(l0, l1);
            lo[ro + 1] = pack_bf16x2(l2, l3);
        }
    }
}

template<bool HP>
__device__ __forceinline__ void compute_stage(const uint32_t* st,
                                              float (&acc)[4][4][4],
                                              int wm0, int wn0, int grp, int qid) {
    const uint32_t* Ah = st;
    const uint32_t* Al = st + TILE_U;
    const uint32_t* Bh = st + 2 * TILE_U;
    const uint32_t* Bl = st + 3 * TILE_U;
#pragma unroll
    for (int ks = 0; ks < 2; ks++) {
        const int kc = ks * 8 + qid;
        uint32_t afh[4][4], afl[4][4];
#pragma unroll
        for (int mf = 0; mf < 4; mf++) {
            int rb = wm0 + mf * 16 + grp;
            afh[mf][0] = Ah[rb * PAD_U + kc];
            afh[mf][1] = Ah[(rb + 8) * PAD_U + kc];
            afh[mf][2] = Ah[rb * PAD_U + kc + 4];
            afh[mf][3] = Ah[(rb + 8) * PAD_U + kc + 4];
            afl[mf][0] = Al[rb * PAD_U + kc];
            afl[mf][1] = Al[(rb + 8) * PAD_U + kc];
            afl[mf][2] = Al[rb * PAD_U + kc + 4];
            afl[mf][3] = Al[(rb + 8) * PAD_U + kc + 4];
        }
#pragma unroll
        for (int nf = 0; nf < 4; nf++) {
            int cb = (wn0 + nf * 8 + grp) * PAD_U;
            uint32_t bh0 = Bh[cb + kc], bh1 = Bh[cb + kc + 4];
            uint32_t bl0 = Bl[cb + kc], bl1 = Bl[cb + kc + 4];
#pragma unroll
            for (int mf = 0; mf < 4; mf++) {
                mma16816(acc[mf][nf], afh[mf], bh0, bh1);  // hi*hi
                mma16816(acc[mf][nf], afl[mf], bh0, bh1);  // lo*hi
                mma16816(acc[mf][nf], afh[mf], bl0, bl1);  // hi*lo
                if (HP) mma16816(acc[mf][nf], afl[mf], bl0, bl1);  // lo*lo
            }
        }
    }
}

// Generic batched TN GEMM:  C[m,n] = sum_k A[m,k]*B[n,k]   (bf16 split, fp32 accum)
// HP:   add lo*lo term (used for QK^T where logits feed softmax)
// MASK: fused scale + causal mask epilogue
template<bool HP, bool MASK>
__global__ __launch_bounds__(256)
void gemm_bf16x3(GemmParams p) {
    extern __shared__ uint32_t sm[];
    const int tid = threadIdx.x;
    const int z = blockIdx.z;
    const int bb = z / p.HB, hh = z % p.HB;
    const float* A  = p.A + (long)bb * p.sAb + (long)hh * p.sAh;
    const float* Bm = p.B + (long)bb * p.sBb + (long)hh * p.sBh;
    float* C        = p.C + (long)bb * p.sCb + (long)hh * p.sCh;
    const int bm0 = blockIdx.y * BM;
    const int bn0 = blockIdx.x * BN;

    const int warp = tid >> 5, lane = tid & 31;
    const int wm0 = (warp >> 2) * 64;   // 2 warps along M
    const int wn0 = (warp & 3) * 32;    // 4 warps along N
    const int grp = lane >> 2, qid = lane & 3;

    const int r0 = tid >> 3;            // staging: row base
    const int c4 = tid & 7;             // staging: float4 column

    float acc[4][4][4];
#pragma unroll
    for (int i = 0; i < 4; i++)
#pragma unroll
        for (int j = 0; j < 4; j++)
#pragma unroll
            for (int r = 0; r < 4; r++) acc[i][j][r] = 0.f;

    const float* Abase = A  + (long)bm0 * p.lda + c4 * 4;
    const float* Bbase = Bm + (long)bn0 * p.ldb + c4 * 4;

    float4 ar[4], br[4];
#pragma unroll
    for (int i = 0; i < 4; i++) {
        ar[i] = *reinterpret_cast<const float4*>(Abase + (long)(r0 + 32 * i) * p.lda);
        br[i] = *reinterpret_cast<const float4*>(Bbase + (long)(r0 + 32 * i) * p.ldb);
    }
    sts_tile(sm, 0, ar, br, r0, c4);
    __syncthreads();

    const int nk = p.K / BK;
    for (int kt = 0; kt < nk; kt++) {
        if (kt + 1 < nk) {
            const float* Ak = Abase + (kt + 1) * BK;
            const float* Bk = Bbase + (kt + 1) * BK;
#pragma unroll
            for (int i = 0; i < 4; i++) {
                ar[i] = *reinterpret_cast<const float4*>(Ak + (long)(r0 + 32 * i) * p.lda);
                br[i] = *reinterpret_cast<const float4*>(Bk + (long)(r0 + 32 * i) * p.ldb);
            }
        }
        compute_stage<HP>(sm + (kt & 1) * STAGE_U, acc, wm0, wn0, grp, qid);
        if (kt + 1 < nk) {
            sts_tile(sm, (kt + 1) & 1, ar, br, r0, c4);
            __syncthreads();
        }
    }

    // epilogue
#pragma unroll
    for (int mf = 0; mf < 4; mf++) {
#pragma unroll
        for (int nf = 0; nf < 4; nf++) {
            int row0 = bm0 + wm0 + mf * 16 + grp;
            int col  = bn0 + wn0 + nf * 8 + qid * 2;
            float v0 = acc[mf][nf][0], v1 = acc[mf][nf][1];
            float v2 = acc[mf][nf][2], v3 = acc[mf][nf][3];
            if (MASK) {
                v0 = v0 * p.scale + ((col     > row0)     ? -1e9f : 0.f);
                v1 = v1 * p.scale + ((col + 1 > row0)     ? -1e9f : 0.f);
                v2 = v2 * p.scale + ((col     > row0 + 8) ? -1e9f : 0.f);
                v3 = v3 * p.scale + ((col + 1 > row0 + 8) ? -1e9f : 0.f);
            }
            float* cp = C + (long)row0 * p.ldc + col;
            *reinterpret_cast<float2*>(cp)                 = make_float2(v0, v1);
            *reinterpret_cast<float2*>(cp + 8l * p.ldc)    = make_float2(v2, v3);
        }
    }
}

// ---------------- RoPE + head scatter (+ V transpose) ----------------
__global__ void rope_scatter(const float* __restrict__ tq, const float* __restrict__ tk,
                             const float* __restrict__ tv, const float* __restrict__ fc,
                             const float* __restrict__ fs, float* __restrict__ q,
                             float* __restrict__ k, float* __restrict__ vT) {
    int idx = blockIdx.x * blockDim.x + threadIdx.x;   // B*S*H*64 = 8388608 threads
    int i = idx & 63;
    int h = (idx >> 6) & 31;
    int s = (idx >> 11) & 2047;
    int b = idx >> 22;
    long inoff = (((long)(b * SQ + s)) * NH + h) * HD;
    float c  = fc[s * NPAIR + i];
    float sn = fs[s * NPAIR + i];
    float q1 = tq[inoff + 2 * i], q2 = tq[inoff + 2 * i + 1];
    float k1 = tk[inoff + 2 * i], k2 = tk[inoff + 2 * i + 1];
    long hoff = (((long)(b * NH + h)) * SQ + s) * HD;
    q[hoff + 2 * i]     = q1 * c - q2 * sn;
    q[hoff + 2 * i + 1] = q1 * sn + q2 * c;
    k[hoff + 2 * i]     = k1 * c - k2 * sn;
    k[hoff + 2 * i + 1] = k1 * sn + k2 * c;
    float v1 = tv[inoff + 2 * i], v2 = tv[inoff + 2 * i + 1];
    long vtoff = (((long)(b * NH + h)) * HD + 2 * i) * SQ + s;
    vT[vtoff]      = v1;
    vT[vtoff + SQ] = v2;
}

// ---------------- row softmax over 2048 (mask already folded in) ----------------
__global__ void softmax_rows(float* __restrict__ scores) {
    float* row = scores + (long)blockIdx.x * SQ;
    const int tid = threadIdx.x;
    float v[8];
    float m = -3.4e38f;
#pragma unroll
    for (int j = 0; j < 8; j++) { v[j] = row[tid + 256 * j]; m = fmaxf(m, v[j]); }
#pragma unroll
    for (int o = 16; o; o >>= 1) m = fmaxf(m, __shfl_xor_sync(0xffffffffu, m, o));
    __shared__ float sred[8];
    __shared__ float ssum[8];
    if ((tid & 31) == 0) sred[tid >> 5] = m;
    __syncthreads();
    float mx = sred[0];
#pragma unroll
    for (int w = 1; w < 8; w++) mx = fmaxf(mx, sred[w]);
    float s = 0.f;
#pragma unroll
    for (int j = 0; j < 8; j++) { v[j] = __expf(v[j] - mx); s += v[j]; }
#pragma unroll
    for (int o = 16; o; o >>= 1) s += __shfl_xor_sync(0xffffffffu, s, o);
    if ((tid & 31) == 0) ssum[tid >> 5] = s;
    __syncthreads();
    float st = 0.f;
#pragma unroll
    for (int w = 0; w < 8; w++) st += ssum[w];
    float inv = 1.f / st;
#pragma unroll
    for (int j = 0; j < 8; j++) row[tid + 256 * j] = v[j] * inv;
}

// ---------------- launch helper ----------------
template<bool HP, bool MASK>
static void launch_gemm(const float* A, const float* B, float* C,
                        int M, int N, int K, int lda, int ldb, int ldc,
                        long sAb, long sAh, long sBb, long sBh, long sCb, long sCh,
                        int HB, int batch, float scale) {
    GemmParams p;
    p.A = A; p.B = B; p.C = C;
    p.K = K; p.lda = lda; p.ldb = ldb; p.ldc = ldc;
    p.sAb = sAb; p.sAh = sAh; p.sBb = sBb; p.sBh = sBh; p.sCb = sCb; p.sCh = sCh;
    p.HB = HB; p.scale = scale;
    cudaFuncSetAttribute(gemm_bf16x3<HP, MASK>,
                         cudaFuncAttributeMaxDynamicSharedMemorySize, SMEM_BYTES);
    dim3 grid(N / BN, M / BM, batch);
    gemm_bf16x3<HP, MASK><<<grid, 256, SMEM_BYTES>>>(p);
}

extern "C" void kernel_launch(void* const* d_in, const int* in_sizes, int n_in,
                              void* d_out, int out_size) {
    const float* x  = (const float*)d_in[0];
    const float* fc = (const float*)d_in[1];
    const float* fs = (const float*)d_in[2];
    // d_in[3] = mask (causal, -1e9): folded analytically in the epilogue
    const float* wq = (const float*)d_in[4];
    const float* wk = (const float*)d_in[5];
    const float* wv = (const float*)d_in[6];
    const float* wo = (const float*)d_in[7];
    // d_in[8], d_in[9] = zero caches, d_in[10] = start_pos (0): not needed
    float* out = (float*)d_out;

    float *tmpq, *tmpk, *tmpv, *q, *k, *vT, *scores;
    cudaGetSymbolAddress((void**)&tmpq,   g_tmpq);
    cudaGetSymbolAddress((void**)&tmpk,   g_tmpk);
    cudaGetSymbolAddress((void**)&tmpv,   g_tmpv);
    cudaGetSymbolAddress((void**)&q,      g_q);
    cudaGetSymbolAddress((void**)&k,      g_k);
    cudaGetSymbolAddress((void**)&vT,     g_vT);
    cudaGetSymbolAddress((void**)&scores, g_scores);
    float* attn = tmpq;   // tmpq is dead after rope_scatter; reuse as attn buffer

    const int MB = BQ * SQ;           // 4096 rows
    const float att_scale = 0.08838834764831845f;  // 1/sqrt(128)

    // 1) QKV projections: [4096,4096] x [4096,4096]^T
    launch_gemm<false,false>(x, wq, tmpq, MB, DIM, DIM, DIM, DIM, DIM, 0,0,0,0,0,0, 1, 1, 1.f);
    launch_gemm<false,false>(x, wk, tmpk, MB, DIM, DIM, DIM, DIM, DIM, 0,0,0,0,0,0, 1, 1, 1.f);
    launch_gemm<false,false>(x, wv, tmpv, MB, DIM, DIM, DIM, DIM, DIM, 0,0,0,0,0,0, 1, 1, 1.f);

    // 2) RoPE + scatter to per-head layouts (+ V transpose)
    rope_scatter<<<(BQ * SQ * NH * NPAIR) / 256, 256>>>(tmpq, tmpk, tmpv, fc, fs, q, k, vT);

    // 3) scores = Q K^T * scale + causal mask  (per head, M=N=2048, K=128; high precision)
    launch_gemm<true,true>(q, k, scores, SQ, SQ, HD, HD, HD, SQ,
                (long)NH * SQ * HD, (long)SQ * HD,
                (long)NH * SQ * HD, (long)SQ * HD,
                (long)NH * SQ * SQ, (long)SQ * SQ,
                NH, NBH, att_scale);

    // 4) softmax rows
    softmax_rows<<<NBH * SQ, 256>>>(scores);

    // 5) attn = P @ V  (per head: M=2048, N=128, K=2048; B = V^T is K-major)
    launch_gemm<false,false>(scores, vT, attn, SQ, HD, SQ, SQ, SQ, DIM,
                (long)NH * SQ * SQ, (long)SQ * SQ,
                (long)NH * HD * SQ, (long)HD * SQ,
                (long)SQ * DIM, (long)HD,
                NH, NBH, 1.f);

    // 6) out = attn @ Wo^T
    launch_gemm<false,false>(attn, wo, out, MB, DIM, DIM, DIM, DIM, DIM, 0,0,0,0,0,0, 1, 1, 1.f);
}

// round 6
// speedup vs baseline: 1.3309x; 1.3309x over previous
#include <cuda_runtime.h>
#include <cuda_bf16.h>
#include <cstdint>

// Problem constants (B=2, S=2048, D=4096, H=32, HD=128)
#define BQ   2
#define SQ   2048
#define DIM  4096
#define NH   32
#define HD   128
#define NBH  (BQ*NH)
#define NPAIR (HD/2)

#define NELEM 16777216ll   // BQ*SQ*DIM == BQ*NH*SQ*HD

// ---------------- scratch (static __device__; total 1.69 GB < 2 GB link limit) ----------------
__device__ __align__(1024) float g_tmpq[NELEM];   // QKV proj outputs; tmpq reused as attn fp32
__device__ __align__(1024) float g_tmpk[NELEM];
__device__ __align__(1024) float g_tmpv[NELEM];
__device__ __align__(1024) __nv_bfloat16 g_xh[NELEM],  g_xl[NELEM];   // also reused for attn split
__device__ __align__(1024) __nv_bfloat16 g_wqh[NELEM], g_wql[NELEM];
__device__ __align__(1024) __nv_bfloat16 g_wkh[NELEM], g_wkl[NELEM];
__device__ __align__(1024) __nv_bfloat16 g_wvh[NELEM], g_wvl[NELEM];
__device__ __align__(1024) __nv_bfloat16 g_woh[NELEM], g_wol[NELEM];
__device__ __align__(1024) __nv_bfloat16 g_qh[NELEM],  g_ql[NELEM];
__device__ __align__(1024) __nv_bfloat16 g_kh[NELEM],  g_kl[NELEM];
__device__ __align__(1024) __nv_bfloat16 g_vth[NELEM], g_vtl[NELEM];
// scores: 1 GB fp32. After softmax, each 2048-fp32 row is overwritten IN PLACE by
// 2048 bf16 hi + 2048 bf16 lo (row layout: [ph(2048) | pl(2048)] as bf16).
__device__ __align__(1024) float g_scores[(size_t)NBH*SQ*SQ];

// ---------------- PTX helpers ----------------
__device__ __forceinline__ uint32_t smem_u32(const void* p) {
    uint32_t a;
    asm("{ .reg .u64 t; cvta.to.shared.u64 t, %1; cvt.u32.u64 %0, t; }" : "=r"(a) : "l"(p));
    return a;
}
__device__ __forceinline__ void cp16(uint32_t s, const void* g) {
    asm volatile("cp.async.cg.shared.global [%0], [%1], 16;" :: "r"(s), "l"(g));
}
__device__ __forceinline__ void cp_commit() { asm volatile("cp.async.commit_group;"); }
template<int N> __device__ __forceinline__ void cp_wait() {
    asm volatile("cp.async.wait_group %0;" :: "n"(N));
}
__device__ __forceinline__ void mma16816(float* c, const uint32_t* a, uint32_t b0, uint32_t b1) {
    asm volatile(
        "mma.sync.aligned.m16n8k16.row.col.f32.bf16.bf16.f32 "
        "{%0,%1,%2,%3}, {%4,%5,%6,%7}, {%8,%9}, {%0,%1,%2,%3};\n"
        : "+f"(c[0]), "+f"(c[1]), "+f"(c[2]), "+f"(c[3])
        : "r"(a[0]), "r"(a[1]), "r"(a[2]), "r"(a[3]), "r"(b0), "r"(b1));
}

// ---------------- GEMM config ----------------
// Tiles: 128x128, BK=32 bf16. Smem row pitch = 20 uint32 (80B, 16B-aligned, conflict-free).
#define PITCH_U 20
#define TILE_U (128*PITCH_U)          // 2560 uints = 10240 B per operand tile
#define STAGE_U (4*TILE_U)            // Ah, Al, Bh, Bl
#define NSTG 3
#define DSMEM (NSTG*STAGE_U*4)        // 122880 B

struct GemmParams {
    const __nv_bfloat16 *Ah, *Al, *Bh, *Bl;
    float* C;
    int K, lda, ldb, ldc, HB;
    long sAb, sAh, sBb, sBh, sCb, sCh;
    float scale;
};

// Load one 128x32 bf16 tile into smem (pitch 20 uints) via cp.async.
__device__ __forceinline__ void ld_tile(const __nv_bfloat16* gb, long ld, int k0,
                                        uint32_t sbyte, int tid) {
#pragma unroll
    for (int j = 0; j < 2; j++) {
        int w = tid + j * 256;           // 0..511
        int row = w >> 2, c4 = w & 3;
        cp16(sbyte + (row * PITCH_U + c4 * 4) * 4,
             gb + (long)row * ld + k0 + c4 * 8);
    }
}

template<bool HP>
__device__ __forceinline__ void compute_stage(const uint32_t* st,
                                              float (&acc)[4][4][4],
                                              int wm0, int wn0, int grp, int qid) {
    const uint32_t* Ah = st;
    const uint32_t* Al = st + TILE_U;
    const uint32_t* Bh = st + 2 * TILE_U;
    const uint32_t* Bl = st + 3 * TILE_U;
#pragma unroll
    for (int ks = 0; ks < 2; ks++) {
        const int kc = ks * 8 + qid;
        uint32_t afh[4][4], afl[4][4];
#pragma unroll
        for (int mf = 0; mf < 4; mf++) {
            int rb = wm0 + mf * 16 + grp;
            afh[mf][0] = Ah[rb * PITCH_U + kc];
            afh[mf][1] = Ah[(rb + 8) * PITCH_U + kc];
            afh[mf][2] = Ah[rb * PITCH_U + kc + 4];
            afh[mf][3] = Ah[(rb + 8) * PITCH_U + kc + 4];
            afl[mf][0] = Al[rb * PITCH_U + kc];
            afl[mf][1] = Al[(rb + 8) * PITCH_U + kc];
            afl[mf][2] = Al[rb * PITCH_U + kc + 4];
            afl[mf][3] = Al[(rb + 8) * PITCH_U + kc + 4];
        }
#pragma unroll
        for (int nf = 0; nf < 4; nf++) {
            int cb = (wn0 + nf * 8 + grp) * PITCH_U;
            uint32_t bh0 = Bh[cb + kc], bh1 = Bh[cb + kc + 4];
            uint32_t bl0 = Bl[cb + kc], bl1 = Bl[cb + kc + 4];
#pragma unroll
            for (int mf = 0; mf < 4; mf++) {
                mma16816(acc[mf][nf], afh[mf], bh0, bh1);            // hi*hi
                mma16816(acc[mf][nf], afl[mf], bh0, bh1);            // lo*hi
                mma16816(acc[mf][nf], afh[mf], bl0, bl1);            // hi*lo
                if (HP) mma16816(acc[mf][nf], afl[mf], bl0, bl1);    // lo*lo
            }
        }
    }
}

// Batched TN GEMM: C[m,n] = sum_k (Ah+Al)[m,k]*(Bh+Bl)[n,k], fp32 accum.
// HP: 4-term (QK^T). MASK: fused scale+causal epilogue + above-diagonal tile skip.
// TRIA: clip K loop to lower triangle (PV, where A=P is causal).
template<bool HP, bool MASK, bool TRIA>
__global__ __launch_bounds__(256, 1)
void gemm_hmma(GemmParams p) {
    extern __shared__ __align__(16) uint32_t sm[];
    const int tid = threadIdx.x;
    const int bm0 = blockIdx.y * 128, bn0 = blockIdx.x * 128;
    const int z = blockIdx.z, bb = z / p.HB, hh = z % p.HB;
    float* C = p.C + (long)bb * p.sCb + (long)hh * p.sCh;

    if (MASK && bn0 > bm0 + 127) {
        float4 m9 = make_float4(-1e9f, -1e9f, -1e9f, -1e9f);
#pragma unroll
        for (int j = 0; j < 16; j++) {
            int idx = tid + j * 256;
            int row = idx >> 5, c4 = idx & 31;
            *reinterpret_cast<float4*>(C + (long)(bm0 + row) * p.ldc + bn0 + c4 * 4) = m9;
        }
        return;
    }

    const __nv_bfloat16* Ah = p.Ah + (long)bb * p.sAb + (long)hh * p.sAh + (long)bm0 * p.lda;
    const __nv_bfloat16* Al = p.Al + (long)bb * p.sAb + (long)hh * p.sAh + (long)bm0 * p.lda;
    const __nv_bfloat16* Bh = p.Bh + (long)bb * p.sBb + (long)hh * p.sBh + (long)bn0 * p.ldb;
    const __nv_bfloat16* Bl = p.Bl + (long)bb * p.sBb + (long)hh * p.sBh + (long)bn0 * p.ldb;

    int nk = p.K >> 5;
    if (TRIA) { int ne = (bm0 >> 5) + 4; if (ne < nk) nk = ne; }   // P lower-triangular

    const int warp = tid >> 5, lane = tid & 31;
    const int wm0 = (warp >> 2) * 64;
    const int wn0 = (warp & 3) * 32;
    const int grp = lane >> 2, qid = lane & 3;

    float acc[4][4][4];
#pragma unroll
    for (int i = 0; i < 4; i++)
#pragma unroll
        for (int j = 0; j < 4; j++)
#pragma unroll
            for (int r = 0; r < 4; r++) acc[i][j][r] = 0.f;

    const uint32_t dsmb = smem_u32(sm);

    // prologue: stages 0, 1  (nk >= 2 always: min K here is 128)
#pragma unroll
    for (int s = 0; s < 2; s++) {
        uint32_t sb = dsmb + s * STAGE_U * 4;
        ld_tile(Ah, p.lda, s * 32, sb,                tid);
        ld_tile(Al, p.lda, s * 32, sb + TILE_U * 4,   tid);
        ld_tile(Bh, p.ldb, s * 32, sb + TILE_U * 8,   tid);
        ld_tile(Bl, p.ldb, s * 32, sb + TILE_U * 12,  tid);
        cp_commit();
    }

    for (int kt = 0; kt < nk; kt++) {
        if (kt + 1 < nk) cp_wait<1>(); else cp_wait<0>();
        __syncthreads();
        if (kt + 2 < nk) {
            int k0 = (kt + 2) * 32;
            uint32_t sb = dsmb + ((kt + 2) % NSTG) * STAGE_U * 4;
            ld_tile(Ah, p.lda, k0, sb,               tid);
            ld_tile(Al, p.lda, k0, sb + TILE_U * 4,  tid);
            ld_tile(Bh, p.ldb, k0, sb + TILE_U * 8,  tid);
            ld_tile(Bl, p.ldb, k0, sb + TILE_U * 12, tid);
            cp_commit();
        }
        compute_stage<HP>(sm + (kt % NSTG) * STAGE_U, acc, wm0, wn0, grp, qid);
        __syncthreads();
    }

    // epilogue
#pragma unroll
    for (int mf = 0; mf < 4; mf++) {
#pragma unroll
        for (int nf = 0; nf < 4; nf++) {
            int row0 = bm0 + wm0 + mf * 16 + grp;
            int col  = bn0 + wn0 + nf * 8 + qid * 2;
            float v0 = acc[mf][nf][0], v1 = acc[mf][nf][1];
            float v2 = acc[mf][nf][2], v3 = acc[mf][nf][3];
            if (MASK) {
                v0 = v0 * p.scale + ((col     > row0)     ? -1e9f : 0.f);
                v1 = v1 * p.scale + ((col + 1 > row0)     ? -1e9f : 0.f);
                v2 = v2 * p.scale + ((col     > row0 + 8) ? -1e9f : 0.f);
                v3 = v3 * p.scale + ((col + 1 > row0 + 8) ? -1e9f : 0.f);
            }
            float* cp = C + (long)row0 * p.ldc + col;
            *reinterpret_cast<float2*>(cp)              = make_float2(v0, v1);
            *reinterpret_cast<float2*>(cp + 8l * p.ldc) = make_float2(v2, v3);
        }
    }
}

// ---------------- elementwise kernels ----------------
__device__ __forceinline__ void split1(float f, __nv_bfloat16& h, __nv_bfloat16& l) {
    h = __float2bfloat16(f);
    l = __float2bfloat16(f - __bfloat162float(h));
}
__device__ __forceinline__ uint32_t pk(__nv_bfloat16 a, __nv_bfloat16 b) {
    return (uint32_t)__bfloat16_as_ushort(a) | ((uint32_t)__bfloat16_as_ushort(b) << 16);
}

__global__ void split4(const float4* __restrict__ src, uint2* __restrict__ hi,
                       uint2* __restrict__ lo) {
    long i = (long)blockIdx.x * blockDim.x + threadIdx.x;
    float4 f = src[i];
    __nv_bfloat16 h0, h1, h2, h3, l0, l1, l2, l3;
    split1(f.x, h0, l0); split1(f.y, h1, l1); split1(f.z, h2, l2); split1(f.w, h3, l3);
    hi[i] = make_uint2(pk(h0, h1), pk(h2, h3));
    lo[i] = make_uint2(pk(l0, l1), pk(l2, l3));
}

__global__ void rope_split(const float* __restrict__ tq, const float* __restrict__ tk,
                           const float* __restrict__ tv, const float* __restrict__ fc,
                           const float* __restrict__ fs,
                           __nv_bfloat16* __restrict__ qh, __nv_bfloat16* __restrict__ ql,
                           __nv_bfloat16* __restrict__ kh, __nv_bfloat16* __restrict__ kl,
                           __nv_bfloat16* __restrict__ vth, __nv_bfloat16* __restrict__ vtl) {
    int idx = blockIdx.x * blockDim.x + threadIdx.x;
    int i = idx & 63;
    int h = (idx >> 6) & 31;
    int s = (idx >> 11) & 2047;
    int b = idx >> 22;
    long inoff = ((long)(b * SQ + s)) * DIM + h * HD;
    float c = fc[s * NPAIR + i], sn = fs[s * NPAIR + i];
    float q1 = tq[inoff + 2 * i], q2 = tq[inoff + 2 * i + 1];
    float k1 = tk[inoff + 2 * i], k2 = tk[inoff + 2 * i + 1];
    float qo1 = q1 * c - q2 * sn, qo2 = q1 * sn + q2 * c;
    float ko1 = k1 * c - k2 * sn, ko2 = k1 * sn + k2 * c;
    long ho = (((long)(b * NH + h)) * SQ + s) * HD + 2 * i;
    __nv_bfloat16 a0, a1, b0, b1;
    split1(qo1, a0, b0); split1(qo2, a1, b1);
    *reinterpret_cast<uint32_t*>(qh + ho) = pk(a0, a1);
    *reinterpret_cast<uint32_t*>(ql + ho) = pk(b0, b1);
    split1(ko1, a0, b0); split1(ko2, a1, b1);
    *reinterpret_cast<uint32_t*>(kh + ho) = pk(a0, a1);
    *reinterpret_cast<uint32_t*>(kl + ho) = pk(b0, b1);
    float v1 = tv[inoff + 2 * i], v2 = tv[inoff + 2 * i + 1];
    long vo = (((long)(b * NH + h)) * HD + 2 * i) * SQ + s;
    split1(v1, a0, b0); split1(v2, a1, b1);
    vth[vo] = a0; vtl[vo] = b0;
    vth[vo + SQ] = a1; vtl[vo + SQ] = b1;
}

// Softmax over a 2048 row, then overwrite the row IN PLACE with [ph(2048 bf16) | pl(2048 bf16)].
// All loads complete before the first __syncthreads(), so in-place overwrite is race-free.
__global__ void softmax_split_inplace(float* __restrict__ sc) {
    long base = (long)blockIdx.x * SQ;
    const int tid = threadIdx.x;
    float4 a = *reinterpret_cast<const float4*>(sc + base + tid * 8);
    float4 b = *reinterpret_cast<const float4*>(sc + base + tid * 8 + 4);
    float v[8] = {a.x, a.y, a.z, a.w, b.x, b.y, b.z, b.w};
    float m = v[0];
#pragma unroll
    for (int j = 1; j < 8; j++) m = fmaxf(m, v[j]);
#pragma unroll
    for (int o = 16; o; o >>= 1) m = fmaxf(m, __shfl_xor_sync(0xffffffffu, m, o));
    __shared__ float sred[8], ssum[8];
    if ((tid & 31) == 0) sred[tid >> 5] = m;
    __syncthreads();                     // <- all row loads complete before this point
    float mx = sred[0];
#pragma unroll
    for (int w = 1; w < 8; w++) mx = fmaxf(mx, sred[w]);
    float s = 0.f;
#pragma unroll
    for (int j = 0; j < 8; j++) { v[j] = __expf(v[j] - mx); s += v[j]; }
#pragma unroll
    for (int o = 16; o; o >>= 1) s += __shfl_xor_sync(0xffffffffu, s, o);
    if ((tid & 31) == 0) ssum[tid >> 5] = s;
    __syncthreads();
    float st = 0.f;
#pragma unroll
    for (int w = 0; w < 8; w++) st += ssum[w];
    float inv = 1.f / st;
    uint32_t hp[4], lp[4];
#pragma unroll
    for (int j = 0; j < 4; j++) {
        __nv_bfloat16 h0, h1, l0, l1;
        split1(v[2 * j] * inv, h0, l0);
        split1(v[2 * j + 1] * inv, h1, l1);
        hp[j] = pk(h0, h1);
        lp[j] = pk(l0, l1);
    }
    __nv_bfloat16* row_bf = reinterpret_cast<__nv_bfloat16*>(sc + base);
    *reinterpret_cast<uint4*>(row_bf + tid * 8)        = make_uint4(hp[0], hp[1], hp[2], hp[3]);
    *reinterpret_cast<uint4*>(row_bf + SQ + tid * 8)   = make_uint4(lp[0], lp[1], lp[2], lp[3]);
}

// ---------------- host side ----------------
template<bool HP, bool MASK, bool TRIA>
static void launch_gemm(const __nv_bfloat16* Ah, const __nv_bfloat16* Al,
                        const __nv_bfloat16* Bh, const __nv_bfloat16* Bl, float* C,
                        int M, int N, int K, int lda, int ldb, int ldc,
                        long sAb, long sAh, long sBb, long sBh, long sCb, long sCh,
                        int HB, int batch, float scale) {
    GemmParams p;
    p.Ah = Ah; p.Al = Al; p.Bh = Bh; p.Bl = Bl; p.C = C;
    p.K = K; p.lda = lda; p.ldb = ldb; p.ldc = ldc; p.HB = HB;
    p.sAb = sAb; p.sAh = sAh; p.sBb = sBb; p.sBh = sBh; p.sCb = sCb; p.sCh = sCh;
    p.scale = scale;
    cudaFuncSetAttribute(gemm_hmma<HP, MASK, TRIA>,
                         cudaFuncAttributeMaxDynamicSharedMemorySize, DSMEM);
    dim3 grid(N / 128, M / 128, batch);
    gemm_hmma<HP, MASK, TRIA><<<grid, 256, DSMEM>>>(p);
}

extern "C" void kernel_launch(void* const* d_in, const int* in_sizes, int n_in,
                              void* d_out, int out_size) {
    const float* x  = (const float*)d_in[0];
    const float* fc = (const float*)d_in[1];
    const float* fs = (const float*)d_in[2];
    const float* wq = (const float*)d_in[4];
    const float* wk = (const float*)d_in[5];
    const float* wv = (const float*)d_in[6];
    const float* wo = (const float*)d_in[7];
    float* out = (float*)d_out;

    float *tmpq, *tmpk, *tmpv, *scores;
    __nv_bfloat16 *xh, *xl, *wqh, *wql, *wkh, *wkl, *wvh, *wvl, *woh, *wol;
    __nv_bfloat16 *qh, *ql, *kh, *kl, *vth, *vtl;
    cudaGetSymbolAddress((void**)&tmpq, g_tmpq);
    cudaGetSymbolAddress((void**)&tmpk, g_tmpk);
    cudaGetSymbolAddress((void**)&tmpv, g_tmpv);
    cudaGetSymbolAddress((void**)&scores, g_scores);
    cudaGetSymbolAddress((void**)&xh, g_xh);   cudaGetSymbolAddress((void**)&xl, g_xl);
    cudaGetSymbolAddress((void**)&wqh, g_wqh); cudaGetSymbolAddress((void**)&wql, g_wql);
    cudaGetSymbolAddress((void**)&wkh, g_wkh); cudaGetSymbolAddress((void**)&wkl, g_wkl);
    cudaGetSymbolAddress((void**)&wvh, g_wvh); cudaGetSymbolAddress((void**)&wvl, g_wvl);
    cudaGetSymbolAddress((void**)&woh, g_woh); cudaGetSymbolAddress((void**)&wol, g_wol);
    cudaGetSymbolAddress((void**)&qh, g_qh);   cudaGetSymbolAddress((void**)&ql, g_ql);
    cudaGetSymbolAddress((void**)&kh, g_kh);   cudaGetSymbolAddress((void**)&kl, g_kl);
    cudaGetSymbolAddress((void**)&vth, g_vth); cudaGetSymbolAddress((void**)&vtl, g_vtl);
    float* attn = tmpq;                 // tmpq dead after rope_split
    __nv_bfloat16* ah = xh;             // xh/xl dead after QKV projections
    __nv_bfloat16* al = xl;
    // P hi/lo live inside the scores buffer (in-place softmax split):
    // per head: 2048 rows, each row = [2048 bf16 hi | 2048 bf16 lo]
    __nv_bfloat16* ph = (__nv_bfloat16*)scores;
    __nv_bfloat16* pl = ph + SQ;

    const int MB = BQ * SQ;                         // 4096
    const int SPLIT_BLK = (int)(NELEM / 4 / 256);   // 16384
    const float att_scale = 0.08838834764831845f;   // 1/sqrt(128)

    // 0) split inputs/weights to bf16 hi/lo
    split4<<<SPLIT_BLK, 256>>>((const float4*)x,  (uint2*)xh,  (uint2*)xl);
    split4<<<SPLIT_BLK, 256>>>((const float4*)wq, (uint2*)wqh, (uint2*)wql);
    split4<<<SPLIT_BLK, 256>>>((const float4*)wk, (uint2*)wkh, (uint2*)wkl);
    split4<<<SPLIT_BLK, 256>>>((const float4*)wv, (uint2*)wvh, (uint2*)wvl);
    split4<<<SPLIT_BLK, 256>>>((const float4*)wo, (uint2*)woh, (uint2*)wol);

    // 1) QKV projections
    launch_gemm<false,false,false>(xh, xl, wqh, wql, tmpq, MB, DIM, DIM, DIM, DIM, DIM,
                                   0,0,0,0,0,0, 1, 1, 1.f);
    launch_gemm<false,false,false>(xh, xl, wkh, wkl, tmpk, MB, DIM, DIM, DIM, DIM, DIM,
                                   0,0,0,0,0,0, 1, 1, 1.f);
    launch_gemm<false,false,false>(xh, xl, wvh, wvl, tmpv, MB, DIM, DIM, DIM, DIM, DIM,
                                   0,0,0,0,0,0, 1, 1, 1.f);

    // 2) RoPE + per-head scatter + split (+ V transpose)
    rope_split<<<(BQ * SQ * NH * NPAIR) / 256, 256>>>(tmpq, tmpk, tmpv, fc, fs,
                                                      qh, ql, kh, kl, vth, vtl);

    // 3) scores = Q K^T * scale + causal mask (HP 4-term; above-diagonal tiles skipped)
    launch_gemm<true,true,false>(qh, ql, kh, kl, scores, SQ, SQ, HD, HD, HD, SQ,
                                 (long)NH * SQ * HD, (long)SQ * HD,
                                 (long)NH * SQ * HD, (long)SQ * HD,
                                 (long)NH * SQ * SQ, (long)SQ * SQ,
                                 NH, NBH, att_scale);

    // 4) softmax + in-place split of P to bf16 hi/lo (row = [hi|lo])
    softmax_split_inplace<<<NBH * SQ, 256>>>(scores);

    // 5) attn = P @ V  (A rows have lda = 2*SQ bf16: [hi|lo]; K-loop clipped to lower triangle)
    launch_gemm<false,false,true>(ph, pl, vth, vtl, attn, SQ, HD, SQ, 2 * SQ, SQ, DIM,
                                  (long)NH * SQ * 2 * SQ, (long)SQ * 2 * SQ,
                                  (long)NH * HD * SQ, (long)HD * SQ,
                                  (long)SQ * DIM, (long)HD,
                                  NH, NBH, 1.f);

    // 6) split attn (into xh/xl, now dead), out = attn @ Wo^T
    split4<<<SPLIT_BLK, 256>>>((const float4*)attn, (uint2*)ah, (uint2*)al);
    launch_gemm<false,false,false>(ah, al, woh, wol, out, MB, DIM, DIM, DIM, DIM, DIM,
                                   0,0,0,0,0,0, 1, 1, 1.f);
}